// round 12
// baseline (speedup 1.0000x reference)
#include <cuda_runtime.h>
#include <cuda_bf16.h>
#include <mma.h>

using namespace nvcuda;

// x:(1024,64,256) f32, mask:(64,64,64) f32, w_qkv:(256,768), b_qkv:(768),
// w_proj:(256,256), b_proj:(256) -> out:(1024,64,256) f32

#define NWIN   1024
#define NTOK   64
#define CDIM   256
#define NHEAD  8
#define HD     32
#define MROWS  (NWIN * NTOK)   // 65536

typedef __nv_bfloat16 bf16;

// Static device scratch (device-code references only).
// Q/K/V stored PRE-SPLIT: one uint per element = packed (hi bf16 | lo bf16<<16).
__device__ __align__(128) unsigned g_Qp[NWIN * NHEAD * NTOK * HD];
__device__ __align__(128) unsigned g_Kp[NWIN * NHEAD * NTOK * HD];
__device__ __align__(128) unsigned g_Vp[NWIN * NHEAD * NTOK * HD];
__device__ __align__(128) float    g_AO[NWIN * NTOK * CDIM];

__device__ __forceinline__ void split_bf16(float x, bf16& hi, bf16& lo) {
    hi = __float2bfloat16_rn(x);
    lo = __float2bfloat16_rn(x - __bfloat162float(hi));
}
__device__ __forceinline__ unsigned pack_split(float x) {
    bf16 h, l; split_bf16(x, h, l);
    return (unsigned)__bfloat16_as_ushort(h) | ((unsigned)__bfloat16_as_ushort(l) << 16);
}
__device__ __forceinline__ unsigned pack2(bf16 a, bf16 b) {
    return (unsigned)__bfloat16_as_ushort(a) | ((unsigned)__bfloat16_as_ushort(b) << 16);
}
__device__ __forceinline__ unsigned prmt(unsigned a, unsigned b, unsigned sel) {
    unsigned d;
    asm("prmt.b32 %0, %1, %2, %3;" : "=r"(d) : "r"(a), "r"(b), "r"(sel));
    return d;
}
// From two packed (hi|lo<<16) words u0,u1: hi-pair = bytes {0,1,4,5}, lo-pair = {2,3,6,7}.
#define SEL_HI 0x5410u
#define SEL_LO 0x7632u

// Split a float4 and store as uint2 hi / uint2 lo (8B stores, addrs must be 8B-aligned).
__device__ __forceinline__ void store_split4(void* ph, void* pl, float4 f) {
    bf16 h0, l0, h1, l1, h2, l2, h3, l3;
    split_bf16(f.x, h0, l0); split_bf16(f.y, h1, l1);
    split_bf16(f.z, h2, l2); split_bf16(f.w, h3, l3);
    *(uint2*)ph = make_uint2(pack2(h0, h1), pack2(h2, h3));
    *(uint2*)pl = make_uint2(pack2(l0, l1), pack2(l2, l3));
}

// ---------------------------------------------------------------------------
// FP32-emulated GEMM via 3x bf16 wmma (R7/R9 config).
// 128x128 CTA tile, K-chunk 32, double-buffered, 512 threads, warp tile 32x32.
// smem planes: hi slots {0,1}=buf, lo slots {2,3}=buf+2.
// MODE 0: A = x; epilogue packs split Q/K/V into g_Qp/g_Kp/g_Vp (Q pre-scaled)
// MODE 1: A = g_AO; plain epilogue to out
// ---------------------------------------------------------------------------
#define SA_STRIDE 40
#define SB_STRIDE 136
#define SA_PLANE  (128 * SA_STRIDE)
#define SB_PLANE  (32 * SB_STRIDE)
#define SA_BYTES  (4 * SA_PLANE * 2)         // 40960 B
#define SB_BYTES  (4 * SB_PLANE * 2)         // 34816 B
#define GEMM_SMEM (SA_BYTES + SB_BYTES)      // 75776 B

template <int LDB, int MODE>
__global__ __launch_bounds__(512, 2)
void gemm_bf16x3_kernel(const float* __restrict__ A,
                        const float* __restrict__ B,
                        const float* __restrict__ bias,
                        float* __restrict__ out)
{
    extern __shared__ __align__(128) char smem_raw[];
    bf16*  sA = (bf16*)smem_raw;
    bf16*  sB = (bf16*)(smem_raw + SA_BYTES);
    float* Cs = (float*)smem_raw;                   // epilogue union, 128x128

    const int tid  = threadIdx.x;
    const int warp = tid >> 5;
    const int wm   = warp & 3;
    const int wn   = warp >> 2;

    const int bm = blockIdx.y;
    const int bn = blockIdx.x * 128;

    const float* Asrc = (MODE == 0) ? A : (const float*)g_AO;
    const float* Ap   = Asrc + (size_t)bm * 128 * CDIM;

    const int a_row0 = tid >> 3,  a_ks = (tid & 7) * 4;
    const int b_k0   = tid >> 5,  b_cs = (tid & 31) * 4;

    wmma::fragment<wmma::accumulator, 16, 16, 16, float> acc[2][2];
    #pragma unroll
    for (int i = 0; i < 2; i++)
        #pragma unroll
        for (int j = 0; j < 2; j++) wmma::fill_fragment(acc[i][j], 0.0f);

    float4 ra[2], rb[2];

    #pragma unroll
    for (int it = 0; it < 2; it++) {
        ra[it] = *(const float4*)(Ap + (size_t)(a_row0 + it * 64) * CDIM + a_ks);
        rb[it] = *(const float4*)(B + (size_t)(b_k0 + it * 16) * LDB + bn + b_cs);
    }
    #pragma unroll
    for (int it = 0; it < 2; it++) {
        int row = a_row0 + it * 64;
        bf16* ah = sA + (size_t)row * SA_STRIDE + a_ks;
        store_split4(ah, ah + 2 * SA_PLANE, ra[it]);
        int k = b_k0 + it * 16;
        bf16* bh = sB + (size_t)k * SB_STRIDE + b_cs;
        store_split4(bh, bh + 2 * SB_PLANE, rb[it]);
    }
    __syncthreads();

    #pragma unroll
    for (int c = 0; c < 8; c++) {
        const int buf = c & 1;
        if (c < 7) {
            const int k0 = (c + 1) * 32;
            #pragma unroll
            for (int it = 0; it < 2; it++) {
                ra[it] = *(const float4*)(Ap + (size_t)(a_row0 + it * 64) * CDIM + k0 + a_ks);
                rb[it] = *(const float4*)(B + (size_t)(k0 + b_k0 + it * 16) * LDB + bn + b_cs);
            }
        }

        #pragma unroll
        for (int kk = 0; kk < 32; kk += 16) {
            wmma::fragment<wmma::matrix_a, 16, 16, 16, bf16, wmma::row_major> ah[2], al[2];
            wmma::fragment<wmma::matrix_b, 16, 16, 16, bf16, wmma::row_major> bh[2], bl[2];
            #pragma unroll
            for (int fi = 0; fi < 2; fi++) {
                const bf16* base = sA + ((size_t)buf * 128 + wm * 32 + fi * 16) * SA_STRIDE + kk;
                wmma::load_matrix_sync(ah[fi], base, SA_STRIDE);
                wmma::load_matrix_sync(al[fi], base + 2 * SA_PLANE, SA_STRIDE);
            }
            #pragma unroll
            for (int fj = 0; fj < 2; fj++) {
                const bf16* base = sB + ((size_t)buf * 32 + kk) * SB_STRIDE + wn * 32 + fj * 16;
                wmma::load_matrix_sync(bh[fj], base, SB_STRIDE);
                wmma::load_matrix_sync(bl[fj], base + 2 * SB_PLANE, SB_STRIDE);
            }
            #pragma unroll
            for (int fi = 0; fi < 2; fi++)
                #pragma unroll
                for (int fj = 0; fj < 2; fj++) {
                    wmma::mma_sync(acc[fi][fj], ah[fi], bh[fj], acc[fi][fj]);
                    wmma::mma_sync(acc[fi][fj], ah[fi], bl[fj], acc[fi][fj]);
                    wmma::mma_sync(acc[fi][fj], al[fi], bh[fj], acc[fi][fj]);
                }
        }

        if (c < 7) {
            const int nb = (c + 1) & 1;
            #pragma unroll
            for (int it = 0; it < 2; it++) {
                int row = a_row0 + it * 64;
                bf16* ahp = sA + ((size_t)nb * 128 + row) * SA_STRIDE + a_ks;
                store_split4(ahp, ahp + 2 * SA_PLANE, ra[it]);
                int k = b_k0 + it * 16;
                bf16* bhp = sB + ((size_t)nb * 32 + k) * SB_STRIDE + b_cs;
                store_split4(bhp, bhp + 2 * SB_PLANE, rb[it]);
            }
            __syncthreads();
        }
    }

    __syncthreads();

    #pragma unroll
    for (int fi = 0; fi < 2; fi++)
        #pragma unroll
        for (int fj = 0; fj < 2; fj++)
            wmma::store_matrix_sync(&Cs[(size_t)(wm * 32 + fi * 16) * 128 + wn * 32 + fj * 16],
                                    acc[fi][fj], 128, wmma::mem_row_major);
    __syncthreads();

    if (MODE == 0) {
        const float scale = 0.17677669529663687f;  // 1/sqrt(32)
        for (int idx = tid; idx < 128 * 128; idx += 512) {
            int i = idx >> 7, jj = idx & 127;
            int j = bn + jj;                         // j = m*256 + h*32 + d
            float v = Cs[(size_t)i * 128 + jj] + bias[j];
            int m = j >> 8, h = (j >> 5) & 7, d = j & 31;
            int r = bm * 128 + i;
            int b = r >> 6, n = r & 63;
            int dst = ((b * NHEAD + h) * NTOK + n) * HD + d;
            if (m == 0)      g_Qp[dst] = pack_split(v * scale);
            else if (m == 1) g_Kp[dst] = pack_split(v);
            else             g_Vp[dst] = pack_split(v);
        }
    } else {
        for (int idx = tid; idx < 128 * 128; idx += 512) {
            int i = idx >> 7, jj = idx & 127;
            out[(size_t)(bm * 128 + i) * CDIM + bn + jj] =
                Cs[(size_t)i * 128 + jj] + bias[bn + jj];
        }
    }
}

// ---------------------------------------------------------------------------
// Attention: one CTA per (window b, head h), 256 threads (8 warps, 4x2 grid).
// Load phase: PRMT repack of packed (hi|lo) words -> wide 8B smem stores.
// Softmax: one warp per row (8 rows/warp), lane l -> cols {2l, 2l+1}:
// float2 coalesced reads, packed uint P writes, shfl-tree reductions.
// ---------------------------------------------------------------------------
struct AttnSmem {
    union {
        struct {
            bf16 Qhi[64][32], Qlo[64][32];
            bf16 Khi[64][32], Klo[64][32];
        } qk;
        struct {
            bf16 Phi[64][64];
            bf16 Plo[64][64];
        } p;
    } u;
    bf16  Vhi[64][32], Vlo[64][32];
    float S[64][64];
};

__global__ __launch_bounds__(256, 4)
void attn_kernel(const float* __restrict__ mask)
{
    __shared__ __align__(128) AttnSmem sm;

    const int tid  = threadIdx.x;
    const int warp = tid >> 5;
    const int lane = tid & 31;
    const int wr   = warp & 3;    // QK/PV row group
    const int wc   = warp >> 2;   // QK/PV col group

    const int bh = blockIdx.x;
    const int b  = bh >> 3;
    const int h  = bh & 7;

    const unsigned* Qg = g_Qp + (size_t)bh * NTOK * HD;
    const unsigned* Kg = g_Kp + (size_t)bh * NTOK * HD;
    const unsigned* Vg = g_Vp + (size_t)bh * NTOK * HD;

    // Load pre-split Q/K/V (512 uint4 each); PRMT repack -> 8B smem stores.
    for (int i = tid; i < 512; i += 256) {
        int r = i >> 3, c = (i & 7) * 4;
        uint4 q = ((const uint4*)Qg)[i];
        uint4 k = ((const uint4*)Kg)[i];
        uint4 v = ((const uint4*)Vg)[i];
        *(uint2*)&sm.u.qk.Qhi[r][c] = make_uint2(prmt(q.x, q.y, SEL_HI), prmt(q.z, q.w, SEL_HI));
        *(uint2*)&sm.u.qk.Qlo[r][c] = make_uint2(prmt(q.x, q.y, SEL_LO), prmt(q.z, q.w, SEL_LO));
        *(uint2*)&sm.u.qk.Khi[r][c] = make_uint2(prmt(k.x, k.y, SEL_HI), prmt(k.z, k.w, SEL_HI));
        *(uint2*)&sm.u.qk.Klo[r][c] = make_uint2(prmt(k.x, k.y, SEL_LO), prmt(k.z, k.w, SEL_LO));
        *(uint2*)&sm.Vhi[r][c]      = make_uint2(prmt(v.x, v.y, SEL_HI), prmt(v.z, v.w, SEL_HI));
        *(uint2*)&sm.Vlo[r][c]      = make_uint2(prmt(v.x, v.y, SEL_LO), prmt(v.z, v.w, SEL_LO));
    }
    __syncthreads();

    // S = Q @ K^T : warp (wr, wc) -> rows wr*16, cols wc*32 (two 16-col tiles)
    {
        wmma::fragment<wmma::accumulator, 16, 16, 16, float> acc[2];
        wmma::fill_fragment(acc[0], 0.0f);
        wmma::fill_fragment(acc[1], 0.0f);
        #pragma unroll
        for (int k = 0; k < 32; k += 16) {
            wmma::fragment<wmma::matrix_a, 16, 16, 16, bf16, wmma::row_major> ah, al;
            wmma::load_matrix_sync(ah, &sm.u.qk.Qhi[wr * 16][k], 32);
            wmma::load_matrix_sync(al, &sm.u.qk.Qlo[wr * 16][k], 32);
            #pragma unroll
            for (int nt = 0; nt < 2; nt++) {
                wmma::fragment<wmma::matrix_b, 16, 16, 16, bf16, wmma::col_major> bh, bl;
                wmma::load_matrix_sync(bh, &sm.u.qk.Khi[wc * 32 + nt * 16][k], 32);
                wmma::load_matrix_sync(bl, &sm.u.qk.Klo[wc * 32 + nt * 16][k], 32);
                wmma::mma_sync(acc[nt], ah, bh, acc[nt]);
                wmma::mma_sync(acc[nt], ah, bl, acc[nt]);
                wmma::mma_sync(acc[nt], al, bh, acc[nt]);
            }
        }
        #pragma unroll
        for (int nt = 0; nt < 2; nt++)
            wmma::store_matrix_sync(&sm.S[wr * 16][wc * 32 + nt * 16], acc[nt], 64,
                                    wmma::mem_row_major);
    }
    __syncthreads();   // S complete; Q/K fragment reads done -> P region free

    // Masked fp32 softmax: warp owns rows warp*8..+7; lane -> cols {2l, 2l+1}.
    {
        const int w = b & 63;
        #pragma unroll
        for (int r8 = 0; r8 < 8; r8++) {
            const int row = warp * 8 + r8;
            const float* mrow = mask + ((size_t)(w * 64 + row)) * 64;
            float2 sv = *(const float2*)&sm.S[row][2 * lane];
            float2 mv = *(const float2*)&mrow[2 * lane];
            float v1 = sv.x + mv.x;
            float v2 = sv.y + mv.y;

            float mx = fmaxf(v1, v2);
            #pragma unroll
            for (int off = 16; off > 0; off >>= 1)
                mx = fmaxf(mx, __shfl_xor_sync(0xffffffffu, mx, off));

            float e1 = __expf(v1 - mx);
            float e2 = __expf(v2 - mx);
            float s = e1 + e2;
            #pragma unroll
            for (int off = 16; off > 0; off >>= 1)
                s += __shfl_xor_sync(0xffffffffu, s, off);

            float inv = 1.0f / s;
            bf16 h1, l1, h2, l2;
            split_bf16(e1 * inv, h1, l1);
            split_bf16(e2 * inv, h2, l2);
            *(unsigned*)&sm.u.p.Phi[row][2 * lane] = pack2(h1, h2);
            *(unsigned*)&sm.u.p.Plo[row][2 * lane] = pack2(l1, l2);
        }
    }
    __syncthreads();

    // O = P @ V : warp (wr, wc) -> rows wr*16, cols wc*16 of the 64x32 output.
    {
        wmma::fragment<wmma::accumulator, 16, 16, 16, float> acc;
        wmma::fill_fragment(acc, 0.0f);
        #pragma unroll
        for (int k = 0; k < 64; k += 16) {
            wmma::fragment<wmma::matrix_a, 16, 16, 16, bf16, wmma::row_major> ph, pl;
            wmma::fragment<wmma::matrix_b, 16, 16, 16, bf16, wmma::row_major> vh, vl;
            wmma::load_matrix_sync(ph, &sm.u.p.Phi[wr * 16][k], 64);
            wmma::load_matrix_sync(pl, &sm.u.p.Plo[wr * 16][k], 64);
            wmma::load_matrix_sync(vh, &sm.Vhi[k][wc * 16], 32);
            wmma::load_matrix_sync(vl, &sm.Vlo[k][wc * 16], 32);
            wmma::mma_sync(acc, ph, vh, acc);
            wmma::mma_sync(acc, ph, vl, acc);
            wmma::mma_sync(acc, pl, vh, acc);
        }
        float* Og = g_AO + (size_t)(b * NTOK) * CDIM + h * HD;
        wmma::store_matrix_sync(Og + (size_t)(wr * 16) * CDIM + wc * 16, acc, CDIM,
                                wmma::mem_row_major);
    }
}

extern "C" void kernel_launch(void* const* d_in, const int* in_sizes, int n_in,
                              void* d_out, int out_size)
{
    const int elems[6] = {16777216, 262144, 196608, 768, 65536, 256};
    const float* p[6] = {nullptr, nullptr, nullptr, nullptr, nullptr, nullptr};
    bool done = false;
    for (int pass = 0; pass < 2 && !done; pass++) {
        long long mult = (pass == 0) ? 1 : 4;
        const float* q[6] = {nullptr, nullptr, nullptr, nullptr, nullptr, nullptr};
        for (int i = 0; i < n_in; i++)
            for (int j = 0; j < 6; j++)
                if ((long long)in_sizes[i] == (long long)elems[j] * mult && q[j] == nullptr)
                    q[j] = (const float*)d_in[i];
        bool all = true;
        for (int j = 0; j < 6; j++) if (q[j] == nullptr) all = false;
        if (all) { for (int j = 0; j < 6; j++) p[j] = q[j]; done = true; }
    }
    if (!done)
        for (int j = 0; j < 6 && j < n_in; j++) p[j] = (const float*)d_in[j];

    const float* x      = p[0];
    const float* mask   = p[1];
    const float* w_qkv  = p[2];
    const float* b_qkv  = p[3];
    const float* w_proj = p[4];
    const float* b_proj = p[5];
    float* out = (float*)d_out;

    cudaFuncSetAttribute(gemm_bf16x3_kernel<768, 0>,
                         cudaFuncAttributeMaxDynamicSharedMemorySize, GEMM_SMEM);
    cudaFuncSetAttribute(gemm_bf16x3_kernel<CDIM, 1>,
                         cudaFuncAttributeMaxDynamicSharedMemorySize, GEMM_SMEM);

    // 1) QKV projection -> pre-split packed g_Qp/g_Kp/g_Vp
    {
        dim3 grid(768 / 128, MROWS / 128);
        gemm_bf16x3_kernel<768, 0><<<grid, 512, GEMM_SMEM>>>(x, w_qkv, b_qkv, nullptr);
    }
    // 2) Windowed attention (PRMT repack + wide stores)
    attn_kernel<<<NWIN * NHEAD, 256>>>(mask);
    // 3) Output projection: g_AO @ w_proj + b_proj -> out
    {
        dim3 grid(CDIM / 128, MROWS / 128);
        gemm_bf16x3_kernel<CDIM, 1><<<grid, 512, GEMM_SMEM>>>(nullptr, w_proj, b_proj, out);
    }
}

// round 13
// speedup vs baseline: 1.3243x; 1.3243x over previous
#include <cuda_runtime.h>
#include <cuda_bf16.h>
#include <cuda_fp16.h>
#include <mma.h>

using namespace nvcuda;

// x:(1024,64,256) f32, mask:(64,64,64) f32, w_qkv:(256,768), b_qkv:(768),
// w_proj:(256,256), b_proj:(256) -> out:(1024,64,256) f32

#define NWIN   1024
#define NTOK   64
#define CDIM   256
#define NHEAD  8
#define HD     32
#define MROWS  (NWIN * NTOK)   // 65536

typedef __nv_bfloat16 bf16;
typedef __half f16;

// Static device scratch (device-code references only).
// Q/K/V stored PRE-SPLIT bf16: uint = (hi bf16 | lo bf16<<16) — attention format.
__device__ __align__(128) unsigned g_Qp[NWIN * NHEAD * NTOK * HD];
__device__ __align__(128) unsigned g_Kp[NWIN * NHEAD * NTOK * HD];
__device__ __align__(128) unsigned g_Vp[NWIN * NHEAD * NTOK * HD];
__device__ __align__(128) float    g_AO[NWIN * NTOK * CDIM];

__device__ __forceinline__ void split_bf16(float x, bf16& hi, bf16& lo) {
    hi = __float2bfloat16_rn(x);
    lo = __float2bfloat16_rn(x - __bfloat162float(hi));
}
__device__ __forceinline__ unsigned pack_split(float x) {
    bf16 h, l; split_bf16(x, h, l);
    return (unsigned)__bfloat16_as_ushort(h) | ((unsigned)__bfloat16_as_ushort(l) << 16);
}
__device__ __forceinline__ void unpack_bf162(unsigned u, bf16& h, bf16& l) {
    h = __ushort_as_bfloat16((unsigned short)(u & 0xffffu));
    l = __ushort_as_bfloat16((unsigned short)(u >> 16));
}
__device__ __forceinline__ void split_f16(float x, f16& hi, f16& lo) {
    hi = __float2half_rn(x);
    lo = __float2half_rn(x - __half2float(hi));
}

// ---------------------------------------------------------------------------
// FP32-emulated GEMM via 2x fp16 wmma:  C ~= Ah*Bh + Ah*Bl  (A cast to fp16,
// B Dekker-split in fp16; residual (A-Ah)*B ~ 2e-4 relative).
// 128x128 CTA tile, K-chunk 32, double-buffered, 512 threads, warp tile 32x32.
// smem: sA hi-only planes {0,1}=buf; sB hi slots {0,1}=buf, lo slots {2,3}=buf+2.
// MODE 0: A = x; epilogue packs bf16-split Q/K/V into g_Qp/g_Kp/g_Vp (Q scaled)
// MODE 1: A = g_AO; plain epilogue to out
// ---------------------------------------------------------------------------
#define SA_STRIDE 40
#define SB_STRIDE 136
#define SA_PLANE  (128 * SA_STRIDE)          // 5120 f16
#define SB_PLANE  (32 * SB_STRIDE)           // 4352 f16
#define SA_BYTES  (2 * SA_PLANE * 2)         // 2 planes  = 20480 B
#define SB_BYTES  (4 * SB_PLANE * 2)         // 4 planes  = 34816 B
#define GEMM_SMEM 65536                      // Cs union (128x128 f32) dominates

template <int LDB, int MODE>
__global__ __launch_bounds__(512, 2)
void gemm_f16x2_kernel(const float* __restrict__ A,
                       const float* __restrict__ B,
                       const float* __restrict__ bias,
                       float* __restrict__ out)
{
    extern __shared__ __align__(128) char smem_raw[];
    f16*   sA = (f16*)smem_raw;
    f16*   sB = (f16*)(smem_raw + SA_BYTES);
    float* Cs = (float*)smem_raw;                   // epilogue union, 128x128

    const int tid  = threadIdx.x;
    const int warp = tid >> 5;
    const int wm   = warp & 3;
    const int wn   = warp >> 2;

    const int bm = blockIdx.y;
    const int bn = blockIdx.x * 128;

    const float* Asrc = (MODE == 0) ? A : (const float*)g_AO;
    const float* Ap   = Asrc + (size_t)bm * 128 * CDIM;

    const int a_row0 = tid >> 3,  a_ks = (tid & 7) * 4;
    const int b_k0   = tid >> 5,  b_cs = (tid & 31) * 4;

    wmma::fragment<wmma::accumulator, 16, 16, 16, float> acc[2][2];
    #pragma unroll
    for (int i = 0; i < 2; i++)
        #pragma unroll
        for (int j = 0; j < 2; j++) wmma::fill_fragment(acc[i][j], 0.0f);

    float4 ra[2], rb[2];

    #pragma unroll
    for (int it = 0; it < 2; it++) {
        ra[it] = *(const float4*)(Ap + (size_t)(a_row0 + it * 64) * CDIM + a_ks);
        rb[it] = *(const float4*)(B + (size_t)(b_k0 + it * 16) * LDB + bn + b_cs);
    }
    #pragma unroll
    for (int it = 0; it < 2; it++) {
        int row = a_row0 + it * 64;
        f16* ah = sA + (size_t)row * SA_STRIDE + a_ks;     // buf0 plane
        ah[0] = __float2half_rn(ra[it].x);
        ah[1] = __float2half_rn(ra[it].y);
        ah[2] = __float2half_rn(ra[it].z);
        ah[3] = __float2half_rn(ra[it].w);
        int k = b_k0 + it * 16;
        f16* bh = sB + (size_t)k * SB_STRIDE + b_cs;       // buf0 hi (slot 0)
        f16* bl = bh + 2 * SB_PLANE;                       // buf0 lo (slot 2)
        split_f16(rb[it].x, bh[0], bl[0]);
        split_f16(rb[it].y, bh[1], bl[1]);
        split_f16(rb[it].z, bh[2], bl[2]);
        split_f16(rb[it].w, bh[3], bl[3]);
    }
    __syncthreads();

    #pragma unroll
    for (int c = 0; c < 8; c++) {
        const int buf = c & 1;
        if (c < 7) {
            const int k0 = (c + 1) * 32;
            #pragma unroll
            for (int it = 0; it < 2; it++) {
                ra[it] = *(const float4*)(Ap + (size_t)(a_row0 + it * 64) * CDIM + k0 + a_ks);
                rb[it] = *(const float4*)(B + (size_t)(k0 + b_k0 + it * 16) * LDB + bn + b_cs);
            }
        }

        #pragma unroll
        for (int kk = 0; kk < 32; kk += 16) {
            wmma::fragment<wmma::matrix_a, 16, 16, 16, f16, wmma::row_major> ah[2];
            wmma::fragment<wmma::matrix_b, 16, 16, 16, f16, wmma::row_major> bh[2], bl[2];
            #pragma unroll
            for (int fi = 0; fi < 2; fi++) {
                const f16* base = sA + ((size_t)buf * 128 + wm * 32 + fi * 16) * SA_STRIDE + kk;
                wmma::load_matrix_sync(ah[fi], base, SA_STRIDE);
            }
            #pragma unroll
            for (int fj = 0; fj < 2; fj++) {
                const f16* base = sB + ((size_t)buf * 32 + kk) * SB_STRIDE + wn * 32 + fj * 16;
                wmma::load_matrix_sync(bh[fj], base, SB_STRIDE);
                wmma::load_matrix_sync(bl[fj], base + 2 * SB_PLANE, SB_STRIDE);
            }
            #pragma unroll
            for (int fi = 0; fi < 2; fi++)
                #pragma unroll
                for (int fj = 0; fj < 2; fj++) {
                    wmma::mma_sync(acc[fi][fj], ah[fi], bh[fj], acc[fi][fj]);
                    wmma::mma_sync(acc[fi][fj], ah[fi], bl[fj], acc[fi][fj]);
                }
        }

        if (c < 7) {
            const int nb = (c + 1) & 1;
            #pragma unroll
            for (int it = 0; it < 2; it++) {
                int row = a_row0 + it * 64;
                f16* ahp = sA + ((size_t)nb * 128 + row) * SA_STRIDE + a_ks;
                ahp[0] = __float2half_rn(ra[it].x);
                ahp[1] = __float2half_rn(ra[it].y);
                ahp[2] = __float2half_rn(ra[it].z);
                ahp[3] = __float2half_rn(ra[it].w);
                int k = b_k0 + it * 16;
                f16* bhp = sB + ((size_t)nb * 32 + k) * SB_STRIDE + b_cs;
                f16* blp = bhp + 2 * SB_PLANE;
                split_f16(rb[it].x, bhp[0], blp[0]);
                split_f16(rb[it].y, bhp[1], blp[1]);
                split_f16(rb[it].z, bhp[2], blp[2]);
                split_f16(rb[it].w, bhp[3], blp[3]);
            }
            __syncthreads();
        }
    }

    __syncthreads();

    #pragma unroll
    for (int fi = 0; fi < 2; fi++)
        #pragma unroll
        for (int fj = 0; fj < 2; fj++)
            wmma::store_matrix_sync(&Cs[(size_t)(wm * 32 + fi * 16) * 128 + wn * 32 + fj * 16],
                                    acc[fi][fj], 128, wmma::mem_row_major);
    __syncthreads();

    if (MODE == 0) {
        const float scale = 0.17677669529663687f;  // 1/sqrt(32)
        for (int idx = tid; idx < 128 * 128; idx += 512) {
            int i = idx >> 7, jj = idx & 127;
            int j = bn + jj;                         // j = m*256 + h*32 + d
            float v = Cs[(size_t)i * 128 + jj] + bias[j];
            int m = j >> 8, h = (j >> 5) & 7, d = j & 31;
            int r = bm * 128 + i;
            int b = r >> 6, n = r & 63;
            int dst = ((b * NHEAD + h) * NTOK + n) * HD + d;
            if (m == 0)      g_Qp[dst] = pack_split(v * scale);
            else if (m == 1) g_Kp[dst] = pack_split(v);
            else             g_Vp[dst] = pack_split(v);
        }
    } else {
        for (int idx = tid; idx < 128 * 128; idx += 512) {
            int i = idx >> 7, jj = idx & 127;
            out[(size_t)(bm * 128 + i) * CDIM + bn + jj] =
                Cs[(size_t)i * 128 + jj] + bias[bn + jj];
        }
    }
}

// ---------------------------------------------------------------------------
// Attention (EXACT R11 version — measured as part of 703.6us): one CTA per
// (window b, head h), 256 threads; bf16x3 mma; one-warp-per-row softmax.
// ---------------------------------------------------------------------------
struct AttnSmem {
    union {
        struct {
            bf16 Qhi[64][32], Qlo[64][32];
            bf16 Khi[64][32], Klo[64][32];
        } qk;
        struct {
            bf16 Phi[64][64];
            bf16 Plo[64][64];
        } p;
    } u;
    bf16  Vhi[64][32], Vlo[64][32];
    float S[64][64];
};

__global__ __launch_bounds__(256, 4)
void attn_kernel(const float* __restrict__ mask)
{
    __shared__ __align__(32) AttnSmem sm;

    const int tid  = threadIdx.x;
    const int warp = tid >> 5;
    const int lane = tid & 31;
    const int wr   = warp & 3;    // QK/PV row group
    const int wc   = warp >> 2;   // QK/PV col group

    const int bh = blockIdx.x;
    const int b  = bh >> 3;
    const int h  = bh & 7;

    const unsigned* Qg = g_Qp + (size_t)bh * NTOK * HD;
    const unsigned* Kg = g_Kp + (size_t)bh * NTOK * HD;
    const unsigned* Vg = g_Vp + (size_t)bh * NTOK * HD;

    for (int i = tid; i < 512; i += 256) {
        int r = i >> 3, c = (i & 7) * 4;
        uint4 q = ((const uint4*)Qg)[i];
        uint4 k = ((const uint4*)Kg)[i];
        uint4 v = ((const uint4*)Vg)[i];
        unpack_bf162(q.x, sm.u.qk.Qhi[r][c+0], sm.u.qk.Qlo[r][c+0]);
        unpack_bf162(q.y, sm.u.qk.Qhi[r][c+1], sm.u.qk.Qlo[r][c+1]);
        unpack_bf162(q.z, sm.u.qk.Qhi[r][c+2], sm.u.qk.Qlo[r][c+2]);
        unpack_bf162(q.w, sm.u.qk.Qhi[r][c+3], sm.u.qk.Qlo[r][c+3]);
        unpack_bf162(k.x, sm.u.qk.Khi[r][c+0], sm.u.qk.Klo[r][c+0]);
        unpack_bf162(k.y, sm.u.qk.Khi[r][c+1], sm.u.qk.Klo[r][c+1]);
        unpack_bf162(k.z, sm.u.qk.Khi[r][c+2], sm.u.qk.Klo[r][c+2]);
        unpack_bf162(k.w, sm.u.qk.Khi[r][c+3], sm.u.qk.Klo[r][c+3]);
        unpack_bf162(v.x, sm.Vhi[r][c+0], sm.Vlo[r][c+0]);
        unpack_bf162(v.y, sm.Vhi[r][c+1], sm.Vlo[r][c+1]);
        unpack_bf162(v.z, sm.Vhi[r][c+2], sm.Vlo[r][c+2]);
        unpack_bf162(v.w, sm.Vhi[r][c+3], sm.Vlo[r][c+3]);
    }
    __syncthreads();

    {
        wmma::fragment<wmma::accumulator, 16, 16, 16, float> acc[2];
        wmma::fill_fragment(acc[0], 0.0f);
        wmma::fill_fragment(acc[1], 0.0f);
        #pragma unroll
        for (int k = 0; k < 32; k += 16) {
            wmma::fragment<wmma::matrix_a, 16, 16, 16, bf16, wmma::row_major> ah, al;
            wmma::load_matrix_sync(ah, &sm.u.qk.Qhi[wr * 16][k], 32);
            wmma::load_matrix_sync(al, &sm.u.qk.Qlo[wr * 16][k], 32);
            #pragma unroll
            for (int nt = 0; nt < 2; nt++) {
                wmma::fragment<wmma::matrix_b, 16, 16, 16, bf16, wmma::col_major> bh, bl;
                wmma::load_matrix_sync(bh, &sm.u.qk.Khi[wc * 32 + nt * 16][k], 32);
                wmma::load_matrix_sync(bl, &sm.u.qk.Klo[wc * 32 + nt * 16][k], 32);
                wmma::mma_sync(acc[nt], ah, bh, acc[nt]);
                wmma::mma_sync(acc[nt], ah, bl, acc[nt]);
                wmma::mma_sync(acc[nt], al, bh, acc[nt]);
            }
        }
        #pragma unroll
        for (int nt = 0; nt < 2; nt++)
            wmma::store_matrix_sync(&sm.S[wr * 16][wc * 32 + nt * 16], acc[nt], 64,
                                    wmma::mem_row_major);
    }
    __syncthreads();

    {
        const int w = b & 63;
        #pragma unroll
        for (int r8 = 0; r8 < 8; r8++) {
            const int row = warp * 8 + r8;
            const float* mrow = mask + ((size_t)(w * 64 + row)) * 64;
            float v1 = sm.S[row][lane]      + mrow[lane];
            float v2 = sm.S[row][lane + 32] + mrow[lane + 32];

            float mx = fmaxf(v1, v2);
            #pragma unroll
            for (int off = 16; off > 0; off >>= 1)
                mx = fmaxf(mx, __shfl_xor_sync(0xffffffffu, mx, off));

            float e1 = __expf(v1 - mx);
            float e2 = __expf(v2 - mx);
            float s = e1 + e2;
            #pragma unroll
            for (int off = 16; off > 0; off >>= 1)
                s += __shfl_xor_sync(0xffffffffu, s, off);

            float inv = 1.0f / s;
            split_bf16(e1 * inv, sm.u.p.Phi[row][lane],      sm.u.p.Plo[row][lane]);
            split_bf16(e2 * inv, sm.u.p.Phi[row][lane + 32], sm.u.p.Plo[row][lane + 32]);
        }
    }
    __syncthreads();

    {
        wmma::fragment<wmma::accumulator, 16, 16, 16, float> acc;
        wmma::fill_fragment(acc, 0.0f);
        #pragma unroll
        for (int k = 0; k < 64; k += 16) {
            wmma::fragment<wmma::matrix_a, 16, 16, 16, bf16, wmma::row_major> ph, pl;
            wmma::fragment<wmma::matrix_b, 16, 16, 16, bf16, wmma::row_major> vh, vl;
            wmma::load_matrix_sync(ph, &sm.u.p.Phi[wr * 16][k], 64);
            wmma::load_matrix_sync(pl, &sm.u.p.Plo[wr * 16][k], 64);
            wmma::load_matrix_sync(vh, &sm.Vhi[k][wc * 16], 32);
            wmma::load_matrix_sync(vl, &sm.Vlo[k][wc * 16], 32);
            wmma::mma_sync(acc, ph, vh, acc);
            wmma::mma_sync(acc, ph, vl, acc);
            wmma::mma_sync(acc, pl, vh, acc);
        }
        float* Og = g_AO + (size_t)(b * NTOK) * CDIM + h * HD;
        wmma::store_matrix_sync(Og + (size_t)(wr * 16) * CDIM + wc * 16, acc, CDIM,
                                wmma::mem_row_major);
    }
}

extern "C" void kernel_launch(void* const* d_in, const int* in_sizes, int n_in,
                              void* d_out, int out_size)
{
    const int elems[6] = {16777216, 262144, 196608, 768, 65536, 256};
    const float* p[6] = {nullptr, nullptr, nullptr, nullptr, nullptr, nullptr};
    bool done = false;
    for (int pass = 0; pass < 2 && !done; pass++) {
        long long mult = (pass == 0) ? 1 : 4;
        const float* q[6] = {nullptr, nullptr, nullptr, nullptr, nullptr, nullptr};
        for (int i = 0; i < n_in; i++)
            for (int j = 0; j < 6; j++)
                if ((long long)in_sizes[i] == (long long)elems[j] * mult && q[j] == nullptr)
                    q[j] = (const float*)d_in[i];
        bool all = true;
        for (int j = 0; j < 6; j++) if (q[j] == nullptr) all = false;
        if (all) { for (int j = 0; j < 6; j++) p[j] = q[j]; done = true; }
    }
    if (!done)
        for (int j = 0; j < 6 && j < n_in; j++) p[j] = (const float*)d_in[j];

    const float* x      = p[0];
    const float* mask   = p[1];
    const float* w_qkv  = p[2];
    const float* b_qkv  = p[3];
    const float* w_proj = p[4];
    const float* b_proj = p[5];
    float* out = (float*)d_out;

    cudaFuncSetAttribute(gemm_f16x2_kernel<768, 0>,
                         cudaFuncAttributeMaxDynamicSharedMemorySize, GEMM_SMEM);
    cudaFuncSetAttribute(gemm_f16x2_kernel<CDIM, 1>,
                         cudaFuncAttributeMaxDynamicSharedMemorySize, GEMM_SMEM);

    // 1) QKV projection -> pre-split packed g_Qp/g_Kp/g_Vp
    {
        dim3 grid(768 / 128, MROWS / 128);
        gemm_f16x2_kernel<768, 0><<<grid, 512, GEMM_SMEM>>>(x, w_qkv, b_qkv, nullptr);
    }
    // 2) Windowed attention (R11 version, unchanged)
    attn_kernel<<<NWIN * NHEAD, 256>>>(mask);
    // 3) Output projection: g_AO @ w_proj + b_proj -> out
    {
        dim3 grid(CDIM / 128, MROWS / 128);
        gemm_f16x2_kernel<CDIM, 1><<<grid, 512, GEMM_SMEM>>>(nullptr, w_proj, b_proj, out);
    }
}

// round 14
// speedup vs baseline: 1.4241x; 1.0754x over previous
#include <cuda_runtime.h>
#include <cuda_bf16.h>
#include <cuda_fp16.h>
#include <mma.h>

using namespace nvcuda;

// x:(1024,64,256) f32, mask:(64,64,64) f32, w_qkv:(256,768), b_qkv:(768),
// w_proj:(256,256), b_proj:(256) -> out:(1024,64,256) f32

#define NWIN   1024
#define NTOK   64
#define CDIM   256
#define NHEAD  8
#define HD     32
#define MROWS  (NWIN * NTOK)   // 65536

typedef __half f16;

// Static device scratch (device-code references only).
// Q: plain fp16 (pre-scaled). K/V: packed (hi f16 | lo f16 << 16) Dekker split.
__device__ __align__(128) f16      g_Qh[NWIN * NHEAD * NTOK * HD];
__device__ __align__(128) unsigned g_Kp[NWIN * NHEAD * NTOK * HD];
__device__ __align__(128) unsigned g_Vp[NWIN * NHEAD * NTOK * HD];
__device__ __align__(128) float    g_AO[NWIN * NTOK * CDIM];

__device__ __forceinline__ void split_f16(float x, f16& hi, f16& lo) {
    hi = __float2half_rn(x);
    lo = __float2half_rn(x - __half2float(hi));
}
__device__ __forceinline__ unsigned pack_split_f16(float x) {
    f16 h, l; split_f16(x, h, l);
    return (unsigned)__half_as_ushort(h) | ((unsigned)__half_as_ushort(l) << 16);
}
__device__ __forceinline__ void unpack_f162(unsigned u, f16& h, f16& l) {
    h = __ushort_as_half((unsigned short)(u & 0xffffu));
    l = __ushort_as_half((unsigned short)(u >> 16));
}

// ---------------------------------------------------------------------------
// FP32-emulated GEMM via 2x fp16 wmma:  C ~= Ah*Bh + Ah*Bl  (R13 — measured
// 285us QKV / ~91us proj). 128x128 CTA tile, K-chunk 32, double-buffered,
// 512 threads, warp tile 32x32.
// MODE 0: A = x; epilogue writes Q (fp16, scaled) / K,V (fp16 split-packed)
// MODE 1: A = g_AO; plain epilogue to out
// ---------------------------------------------------------------------------
#define SA_STRIDE 40
#define SB_STRIDE 136
#define SA_PLANE  (128 * SA_STRIDE)
#define SB_PLANE  (32 * SB_STRIDE)
#define SA_BYTES  (2 * SA_PLANE * 2)         // 20480 B
#define SB_BYTES  (4 * SB_PLANE * 2)         // 34816 B
#define GEMM_SMEM 65536                      // Cs union (128x128 f32) dominates

template <int LDB, int MODE>
__global__ __launch_bounds__(512, 2)
void gemm_f16x2_kernel(const float* __restrict__ A,
                       const float* __restrict__ B,
                       const float* __restrict__ bias,
                       float* __restrict__ out)
{
    extern __shared__ __align__(128) char smem_raw[];
    f16*   sA = (f16*)smem_raw;
    f16*   sB = (f16*)(smem_raw + SA_BYTES);
    float* Cs = (float*)smem_raw;                   // epilogue union, 128x128

    const int tid  = threadIdx.x;
    const int warp = tid >> 5;
    const int wm   = warp & 3;
    const int wn   = warp >> 2;

    const int bm = blockIdx.y;
    const int bn = blockIdx.x * 128;

    const float* Asrc = (MODE == 0) ? A : (const float*)g_AO;
    const float* Ap   = Asrc + (size_t)bm * 128 * CDIM;

    const int a_row0 = tid >> 3,  a_ks = (tid & 7) * 4;
    const int b_k0   = tid >> 5,  b_cs = (tid & 31) * 4;

    wmma::fragment<wmma::accumulator, 16, 16, 16, float> acc[2][2];
    #pragma unroll
    for (int i = 0; i < 2; i++)
        #pragma unroll
        for (int j = 0; j < 2; j++) wmma::fill_fragment(acc[i][j], 0.0f);

    float4 ra[2], rb[2];

    #pragma unroll
    for (int it = 0; it < 2; it++) {
        ra[it] = *(const float4*)(Ap + (size_t)(a_row0 + it * 64) * CDIM + a_ks);
        rb[it] = *(const float4*)(B + (size_t)(b_k0 + it * 16) * LDB + bn + b_cs);
    }
    #pragma unroll
    for (int it = 0; it < 2; it++) {
        int row = a_row0 + it * 64;
        f16* ah = sA + (size_t)row * SA_STRIDE + a_ks;
        ah[0] = __float2half_rn(ra[it].x);
        ah[1] = __float2half_rn(ra[it].y);
        ah[2] = __float2half_rn(ra[it].z);
        ah[3] = __float2half_rn(ra[it].w);
        int k = b_k0 + it * 16;
        f16* bh = sB + (size_t)k * SB_STRIDE + b_cs;
        f16* bl = bh + 2 * SB_PLANE;
        split_f16(rb[it].x, bh[0], bl[0]);
        split_f16(rb[it].y, bh[1], bl[1]);
        split_f16(rb[it].z, bh[2], bl[2]);
        split_f16(rb[it].w, bh[3], bl[3]);
    }
    __syncthreads();

    #pragma unroll
    for (int c = 0; c < 8; c++) {
        const int buf = c & 1;
        if (c < 7) {
            const int k0 = (c + 1) * 32;
            #pragma unroll
            for (int it = 0; it < 2; it++) {
                ra[it] = *(const float4*)(Ap + (size_t)(a_row0 + it * 64) * CDIM + k0 + a_ks);
                rb[it] = *(const float4*)(B + (size_t)(k0 + b_k0 + it * 16) * LDB + bn + b_cs);
            }
        }

        #pragma unroll
        for (int kk = 0; kk < 32; kk += 16) {
            wmma::fragment<wmma::matrix_a, 16, 16, 16, f16, wmma::row_major> ah[2];
            wmma::fragment<wmma::matrix_b, 16, 16, 16, f16, wmma::row_major> bh[2], bl[2];
            #pragma unroll
            for (int fi = 0; fi < 2; fi++) {
                const f16* base = sA + ((size_t)buf * 128 + wm * 32 + fi * 16) * SA_STRIDE + kk;
                wmma::load_matrix_sync(ah[fi], base, SA_STRIDE);
            }
            #pragma unroll
            for (int fj = 0; fj < 2; fj++) {
                const f16* base = sB + ((size_t)buf * 32 + kk) * SB_STRIDE + wn * 32 + fj * 16;
                wmma::load_matrix_sync(bh[fj], base, SB_STRIDE);
                wmma::load_matrix_sync(bl[fj], base + 2 * SB_PLANE, SB_STRIDE);
            }
            #pragma unroll
            for (int fi = 0; fi < 2; fi++)
                #pragma unroll
                for (int fj = 0; fj < 2; fj++) {
                    wmma::mma_sync(acc[fi][fj], ah[fi], bh[fj], acc[fi][fj]);
                    wmma::mma_sync(acc[fi][fj], ah[fi], bl[fj], acc[fi][fj]);
                }
        }

        if (c < 7) {
            const int nb = (c + 1) & 1;
            #pragma unroll
            for (int it = 0; it < 2; it++) {
                int row = a_row0 + it * 64;
                f16* ahp = sA + ((size_t)nb * 128 + row) * SA_STRIDE + a_ks;
                ahp[0] = __float2half_rn(ra[it].x);
                ahp[1] = __float2half_rn(ra[it].y);
                ahp[2] = __float2half_rn(ra[it].z);
                ahp[3] = __float2half_rn(ra[it].w);
                int k = b_k0 + it * 16;
                f16* bhp = sB + ((size_t)nb * 32 + k) * SB_STRIDE + b_cs;
                f16* blp = bhp + 2 * SB_PLANE;
                split_f16(rb[it].x, bhp[0], blp[0]);
                split_f16(rb[it].y, bhp[1], blp[1]);
                split_f16(rb[it].z, bhp[2], blp[2]);
                split_f16(rb[it].w, bhp[3], blp[3]);
            }
            __syncthreads();
        }
    }

    __syncthreads();

    #pragma unroll
    for (int fi = 0; fi < 2; fi++)
        #pragma unroll
        for (int fj = 0; fj < 2; fj++)
            wmma::store_matrix_sync(&Cs[(size_t)(wm * 32 + fi * 16) * 128 + wn * 32 + fj * 16],
                                    acc[fi][fj], 128, wmma::mem_row_major);
    __syncthreads();

    if (MODE == 0) {
        const float scale = 0.17677669529663687f;  // 1/sqrt(32)
        for (int idx = tid; idx < 128 * 128; idx += 512) {
            int i = idx >> 7, jj = idx & 127;
            int j = bn + jj;                         // j = m*256 + h*32 + d
            float v = Cs[(size_t)i * 128 + jj] + bias[j];
            int m = j >> 8, h = (j >> 5) & 7, d = j & 31;
            int r = bm * 128 + i;
            int b = r >> 6, n = r & 63;
            int dst = ((b * NHEAD + h) * NTOK + n) * HD + d;
            if (m == 0)      g_Qh[dst] = __float2half_rn(v * scale);
            else if (m == 1) g_Kp[dst] = pack_split_f16(v);
            else             g_Vp[dst] = pack_split_f16(v);
        }
    } else {
        for (int idx = tid; idx < 128 * 128; idx += 512) {
            int i = idx >> 7, jj = idx & 127;
            out[(size_t)(bm * 128 + i) * CDIM + bn + jj] =
                Cs[(size_t)i * 128 + jj] + bias[bn + jj];
        }
    }
}

// ---------------------------------------------------------------------------
// Attention: one CTA per (window b, head h), 256 threads (8 warps, 4x2 grid).
// fp16 2-term scheme: S = Qh*(Kh + Kl)  (Q cast, K split);
//                     O = Ph*(Vh + Vl)  (P cast, V split).
// 16 mma/warp (was 24). One-warp-per-row softmax (R11, verified).
// ---------------------------------------------------------------------------
struct AttnSmem {
    union {
        struct {                      // phase 1
            f16 Qh [64][32];
            f16 Khi[64][32], Klo[64][32];
        } qk;
        struct {                      // phase 2
            f16 Ph[64][64];
        } p;
    } u;
    f16   Vhi[64][32], Vlo[64][32];
    float S[64][64];
};

__global__ __launch_bounds__(256, 4)
void attn_kernel(const float* __restrict__ mask)
{
    __shared__ __align__(128) AttnSmem sm;

    const int tid  = threadIdx.x;
    const int warp = tid >> 5;
    const int lane = tid & 31;
    const int wr   = warp & 3;    // QK/PV row group
    const int wc   = warp >> 2;   // QK/PV col group

    const int bh = blockIdx.x;
    const int b  = bh >> 3;
    const int h  = bh & 7;

    const f16*      Qg = g_Qh + (size_t)bh * NTOK * HD;
    const unsigned* Kg = g_Kp + (size_t)bh * NTOK * HD;
    const unsigned* Vg = g_Vp + (size_t)bh * NTOK * HD;

    // Q: 2048 fp16 = 256 uint4 — direct copy (no unpack).
    for (int i = tid; i < 256; i += 256) {
        int r = i >> 2, c = (i & 3) * 8;
        *(uint4*)&sm.u.qk.Qh[r][c] = ((const uint4*)Qg)[i];
    }
    // K/V: 2048 packed uints each = 512 uint4; unpack into hi/lo planes.
    for (int i = tid; i < 512; i += 256) {
        int r = i >> 3, c = (i & 7) * 4;
        uint4 k = ((const uint4*)Kg)[i];
        uint4 v = ((const uint4*)Vg)[i];
        unpack_f162(k.x, sm.u.qk.Khi[r][c+0], sm.u.qk.Klo[r][c+0]);
        unpack_f162(k.y, sm.u.qk.Khi[r][c+1], sm.u.qk.Klo[r][c+1]);
        unpack_f162(k.z, sm.u.qk.Khi[r][c+2], sm.u.qk.Klo[r][c+2]);
        unpack_f162(k.w, sm.u.qk.Khi[r][c+3], sm.u.qk.Klo[r][c+3]);
        unpack_f162(v.x, sm.Vhi[r][c+0], sm.Vlo[r][c+0]);
        unpack_f162(v.y, sm.Vhi[r][c+1], sm.Vlo[r][c+1]);
        unpack_f162(v.z, sm.Vhi[r][c+2], sm.Vlo[r][c+2]);
        unpack_f162(v.w, sm.Vhi[r][c+3], sm.Vlo[r][c+3]);
    }
    __syncthreads();

    // S = Q @ K^T : warp (wr, wc) -> rows wr*16, cols wc*32 (two 16-col tiles)
    {
        wmma::fragment<wmma::accumulator, 16, 16, 16, float> acc[2];
        wmma::fill_fragment(acc[0], 0.0f);
        wmma::fill_fragment(acc[1], 0.0f);
        #pragma unroll
        for (int k = 0; k < 32; k += 16) {
            wmma::fragment<wmma::matrix_a, 16, 16, 16, f16, wmma::row_major> aq;
            wmma::load_matrix_sync(aq, &sm.u.qk.Qh[wr * 16][k], 32);
            #pragma unroll
            for (int nt = 0; nt < 2; nt++) {
                wmma::fragment<wmma::matrix_b, 16, 16, 16, f16, wmma::col_major> bh, bl;
                wmma::load_matrix_sync(bh, &sm.u.qk.Khi[wc * 32 + nt * 16][k], 32);
                wmma::load_matrix_sync(bl, &sm.u.qk.Klo[wc * 32 + nt * 16][k], 32);
                wmma::mma_sync(acc[nt], aq, bh, acc[nt]);
                wmma::mma_sync(acc[nt], aq, bl, acc[nt]);
            }
        }
        #pragma unroll
        for (int nt = 0; nt < 2; nt++)
            wmma::store_matrix_sync(&sm.S[wr * 16][wc * 32 + nt * 16], acc[nt], 64,
                                    wmma::mem_row_major);
    }
    __syncthreads();   // S complete; Q/K plane reads done -> P region free

    // Masked fp32 softmax: warp owns rows warp*8..+7; lane -> cols {lane, lane+32}.
    {
        const int w = b & 63;
        #pragma unroll
        for (int r8 = 0; r8 < 8; r8++) {
            const int row = warp * 8 + r8;
            const float* mrow = mask + ((size_t)(w * 64 + row)) * 64;
            float v1 = sm.S[row][lane]      + mrow[lane];
            float v2 = sm.S[row][lane + 32] + mrow[lane + 32];

            float mx = fmaxf(v1, v2);
            #pragma unroll
            for (int off = 16; off > 0; off >>= 1)
                mx = fmaxf(mx, __shfl_xor_sync(0xffffffffu, mx, off));

            float e1 = __expf(v1 - mx);
            float e2 = __expf(v2 - mx);
            float s = e1 + e2;
            #pragma unroll
            for (int off = 16; off > 0; off >>= 1)
                s += __shfl_xor_sync(0xffffffffu, s, off);

            float inv = 1.0f / s;
            sm.u.p.Ph[row][lane]      = __float2half_rn(e1 * inv);
            sm.u.p.Ph[row][lane + 32] = __float2half_rn(e2 * inv);
        }
    }
    __syncthreads();

    // O = P @ V : warp (wr, wc) -> rows wr*16, cols wc*16 of the 64x32 output.
    {
        wmma::fragment<wmma::accumulator, 16, 16, 16, float> acc;
        wmma::fill_fragment(acc, 0.0f);
        #pragma unroll
        for (int k = 0; k < 64; k += 16) {
            wmma::fragment<wmma::matrix_a, 16, 16, 16, f16, wmma::row_major> pf;
            wmma::fragment<wmma::matrix_b, 16, 16, 16, f16, wmma::row_major> vh, vl;
            wmma::load_matrix_sync(pf, &sm.u.p.Ph[wr * 16][k], 64);
            wmma::load_matrix_sync(vh, &sm.Vhi[k][wc * 16], 32);
            wmma::load_matrix_sync(vl, &sm.Vlo[k][wc * 16], 32);
            wmma::mma_sync(acc, pf, vh, acc);
            wmma::mma_sync(acc, pf, vl, acc);
        }
        float* Og = g_AO + (size_t)(b * NTOK) * CDIM + h * HD;
        wmma::store_matrix_sync(Og + (size_t)(wr * 16) * CDIM + wc * 16, acc, CDIM,
                                wmma::mem_row_major);
    }
}

extern "C" void kernel_launch(void* const* d_in, const int* in_sizes, int n_in,
                              void* d_out, int out_size)
{
    const int elems[6] = {16777216, 262144, 196608, 768, 65536, 256};
    const float* p[6] = {nullptr, nullptr, nullptr, nullptr, nullptr, nullptr};
    bool done = false;
    for (int pass = 0; pass < 2 && !done; pass++) {
        long long mult = (pass == 0) ? 1 : 4;
        const float* q[6] = {nullptr, nullptr, nullptr, nullptr, nullptr, nullptr};
        for (int i = 0; i < n_in; i++)
            for (int j = 0; j < 6; j++)
                if ((long long)in_sizes[i] == (long long)elems[j] * mult && q[j] == nullptr)
                    q[j] = (const float*)d_in[i];
        bool all = true;
        for (int j = 0; j < 6; j++) if (q[j] == nullptr) all = false;
        if (all) { for (int j = 0; j < 6; j++) p[j] = q[j]; done = true; }
    }
    if (!done)
        for (int j = 0; j < 6 && j < n_in; j++) p[j] = (const float*)d_in[j];

    const float* x      = p[0];
    const float* mask   = p[1];
    const float* w_qkv  = p[2];
    const float* b_qkv  = p[3];
    const float* w_proj = p[4];
    const float* b_proj = p[5];
    float* out = (float*)d_out;

    cudaFuncSetAttribute(gemm_f16x2_kernel<768, 0>,
                         cudaFuncAttributeMaxDynamicSharedMemorySize, GEMM_SMEM);
    cudaFuncSetAttribute(gemm_f16x2_kernel<CDIM, 1>,
                         cudaFuncAttributeMaxDynamicSharedMemorySize, GEMM_SMEM);

    // 1) QKV projection -> g_Qh (fp16, scaled) / g_Kp, g_Vp (fp16 split-packed)
    {
        dim3 grid(768 / 128, MROWS / 128);
        gemm_f16x2_kernel<768, 0><<<grid, 512, GEMM_SMEM>>>(x, w_qkv, b_qkv, nullptr);
    }
    // 2) Windowed attention (fp16 2-term)
    attn_kernel<<<NWIN * NHEAD, 256>>>(mask);
    // 3) Output projection: g_AO @ w_proj + b_proj -> out
    {
        dim3 grid(CDIM / 128, MROWS / 128);
        gemm_f16x2_kernel<CDIM, 1><<<grid, 512, GEMM_SMEM>>>(nullptr, w_proj, b_proj, out);
    }
}